// round 12
// baseline (speedup 1.0000x reference)
#include <cuda_runtime.h>
#include <math.h>

#define BATCH 2048
typedef unsigned long long ull;

// ---------------------------------------------------------------------------
// f32x2 packed helpers (sm_100+)
// ---------------------------------------------------------------------------
__device__ __forceinline__ ull pk2(float a, float b) {
    ull r;
    asm("mov.b64 %0, {%1, %2};" : "=l"(r) : "f"(a), "f"(b));
    return r;
}
__device__ __forceinline__ void upk2(ull v, float& a, float& b) {
    asm("mov.b64 {%0, %1}, %2;" : "=f"(a), "=f"(b) : "l"(v));
}
__device__ __forceinline__ ull fma2(ull a, ull b, ull c) {
    ull d;
    asm("fma.rn.f32x2 %0, %1, %2, %3;" : "=l"(d) : "l"(a), "l"(b), "l"(c));
    return d;
}

// ---------------------------------------------------------------------------
// Packed weight bank (weights stay as (co,co+1) pairs; activations get
// duplicated in smem instead)
// ---------------------------------------------------------------------------
struct CW {
    ulonglong2 w1[108];   // conv1  [(ci*9+k)*4 + pp]
    ulonglong2 w2[288];   // conv2  [(ci*9+k)*2 + pp]
    ulonglong2 wy[288];   // dconv1 [(ci*9+k)*4 + pp]
    ull        wdp[144];  // dconv2 (co0,co1) [ci*9+k]
    float      wds[144];  // dconv2 co2       [ci*9+k]
};
__device__ CW g_pk;
__constant__ CW c_w;

// Scratch
__device__ float g_part[BATCH * 8];
__device__ float g_q[BATCH * 4];
__device__ float g_Y[5 * 16 * 1024];
__device__ float2 g_V[256];

// ---------------------------------------------------------------------------
// Setup: repack weights; block 7 builds the fixed 16x16 entangling unitary.
// ---------------------------------------------------------------------------
__device__ __forceinline__ float2 cmul(float2 a, float2 b) {
    return make_float2(a.x * b.x - a.y * b.y, a.x * b.y + a.y * b.x);
}

__global__ __launch_bounds__(256) void setup_kernel(
    const float* __restrict__ c1w, const float* __restrict__ c2w,
    const float* __restrict__ d1w, const float* __restrict__ d2w,
    const float* __restrict__ qw, float2* __restrict__ V)
{
    if (blockIdx.x == 7) {
        const int tid = threadIdx.x;
        if (tid >= 16) return;
        float2 st[16];
#pragma unroll
        for (int i = 0; i < 16; i++) st[i] = make_float2(0.f, 0.f);
        st[tid].x = 1.f;
#pragma unroll
        for (int l = 0; l < 3; l++) {
#pragma unroll
            for (int w = 0; w < 4; w++) {
                float phi = qw[(l * 4 + w) * 3 + 0];
                float th  = qw[(l * 4 + w) * 3 + 1];
                float om  = qw[(l * 4 + w) * 3 + 2];
                float ct = cosf(th * 0.5f), stt = sinf(th * 0.5f);
                float a = (phi + om) * 0.5f, d = (phi - om) * 0.5f;
                float ca = cosf(a), sa = sinf(a), cd = cosf(d), sd = sinf(d);
                float2 U00 = make_float2(ct * ca, -ct * sa);
                float2 U01 = make_float2(-stt * cd, -stt * sd);
                float2 U10 = make_float2(stt * cd, -stt * sd);
                float2 U11 = make_float2(ct * ca, ct * sa);
                const int bit = 1 << (3 - w);
#pragma unroll
                for (int i = 0; i < 16; i++) {
                    if (i & bit) continue;
                    float2 a0 = st[i], a1 = st[i | bit];
                    float2 n0 = cmul(U00, a0), n1 = cmul(U10, a0);
                    float2 m0 = cmul(U01, a1), m1 = cmul(U11, a1);
                    st[i]       = make_float2(n0.x + m0.x, n0.y + m0.y);
                    st[i | bit] = make_float2(n1.x + m1.x, n1.y + m1.y);
                }
            }
            const int r = (l % 3) + 1;
#pragma unroll
            for (int w = 0; w < 4; w++) {
                const int cb = 1 << (3 - w);
                const int tb = 1 << (3 - ((w + r) & 3));
#pragma unroll
                for (int i = 0; i < 16; i++) {
                    if ((i & cb) && !(i & tb)) {
                        float2 tmp = st[i]; st[i] = st[i | tb]; st[i | tb] = tmp;
                    }
                }
            }
        }
#pragma unroll
        for (int i = 0; i < 16; i++) V[i * 16 + tid] = st[i];
        return;
    }

    int i = blockIdx.x * 256 + threadIdx.x;
    float* pkf = (float*)&g_pk;
    // float-offset map: w1 @0, w2 @432, wy @1584, wdp @2736, wds @3024
    if (i < 216) {                                  // conv1: 3*9*8 pairs
        int p = i & 7, t = i >> 3;
        int k = t % 9, ci = t / 9;
        pkf[2 * i]     = c1w[(2 * p) * 27 + ci * 9 + k];
        pkf[2 * i + 1] = c1w[(2 * p + 1) * 27 + ci * 9 + k];
    } else if (i < 792) {                           // conv2: 16*9*4 pairs
        int j = i - 216;
        int p = j & 3, t = j >> 2;
        int k = t % 9, ci = t / 9;
        pkf[432 + 2 * j]     = c2w[(2 * p) * 144 + ci * 9 + k];
        pkf[432 + 2 * j + 1] = c2w[(2 * p + 1) * 144 + ci * 9 + k];
    } else if (i < 1368) {                          // dconv1: 8*9*8 pairs
        int j = i - 792;
        int p = j & 7, t = j >> 3;
        int k = t % 9, ci = t / 9;
        pkf[1584 + 2 * j]     = d1w[(2 * p) * 72 + ci * 9 + k];
        pkf[1584 + 2 * j + 1] = d1w[(2 * p + 1) * 72 + ci * 9 + k];
    } else if (i < 1512) {                          // dconv2 pair (co0,co1)
        int j = i - 1368;
        int k = j % 9, ci = j / 9;
        pkf[2736 + 2 * j]     = d2w[ci * 9 + k];
        pkf[2736 + 2 * j + 1] = d2w[144 + ci * 9 + k];
    } else if (i < 1656) {                          // dconv2 scalar co2
        int j = i - 1512;
        pkf[3024 + j] = d2w[288 + j];
    }
}

// ---------------------------------------------------------------------------
// No-op probe: shifts the ncu capture window so conv12 lands in it.
// ---------------------------------------------------------------------------
__global__ void probe_kernel() {}

// ---------------------------------------------------------------------------
// Fused conv1+conv2+fc: 16-row chunks, 512 threads.
// Activations stored DUPLICATED (8B (v,v) pairs) so fma2 operands come
// straight from LDS.64 — zero lane-duplication MOVs in the inner loops.
//   s_x  dup: 3*20*34  ull = 16.3 KB
//   s_h1 dup: 16*18*34 ull = 78.3 KB     total 94.6 KB dynamic, 2 blocks/SM
// ---------------------------------------------------------------------------
#define XDUP   2040    // 3*20*34
#define H1DUP  9792    // 16*18*34
__global__ __launch_bounds__(512) void conv12_kernel(
    const float* __restrict__ in, const float* __restrict__ b1,
    const float* __restrict__ b2, const float* __restrict__ fcw,
    float* __restrict__ part)
{
    extern __shared__ ull dsm[];
    ull* s_x  = dsm;            // [ci][r<20][c<34]
    ull* s_h1 = dsm + XDUP;     // [ch][r<18][c<34]
    __shared__ float s_b1[16];
    __shared__ float s_b2[8];
    __shared__ float swp[16][4];

    const int b  = blockIdx.y;
    const int ck = blockIdx.x;
    const int y0 = ck * 16;
    const int tid = threadIdx.x;

    if (tid < 16) s_b1[tid] = b1[tid];
    else if (tid < 24) s_b2[tid - 16] = b2[tid - 16];

    const float* inb = in + (size_t)b * 3 * 1024;
    for (int i = tid; i < XDUP; i += 512) {
        int c = i / 680, rem = i - c * 680;
        int r = rem / 34, xc = rem - r * 34;
        int gy = y0 - 2 + r, gx = xc - 1;
        float v = 0.f;
        if ((unsigned)gy < 32u && (unsigned)gx < 32u) v = inb[c * 1024 + gy * 32 + gx];
        s_x[i] = pk2(v, v);
    }
    // zero h1 col halo (18 rows x {0,33})
    if (tid < 36) {
        int hr = tid >> 1, xc = (tid & 1) ? 33 : 0;
#pragma unroll
        for (int c = 0; c < 16; c++) s_h1[c * 612 + hr * 34 + xc] = 0ull;
    }
    __syncthreads();

    // ---- conv1: 576 items (18 rows x 32 cols), strided over 512 threads ----
    for (int it = tid; it < 576; it += 512) {
        const int hr = it >> 5, col = it & 31;
        const int gy = y0 - 1 + hr;
        if ((unsigned)gy < 32u) {
            ull acc[8];
#pragma unroll
            for (int p = 0; p < 8; p++) acc[p] = pk2(s_b1[2 * p], s_b1[2 * p + 1]);
#pragma unroll
            for (int ci = 0; ci < 3; ci++) {
                ull v[9];
#pragma unroll
                for (int dy = 0; dy < 3; dy++)
#pragma unroll
                    for (int dx = 0; dx < 3; dx++)
                        v[dy * 3 + dx] = s_x[ci * 680 + (hr + dy) * 34 + col + dx];
#pragma unroll
                for (int k = 0; k < 9; k++) {
#pragma unroll
                    for (int pp = 0; pp < 4; pp++) {
                        ulonglong2 W = c_w.w1[(ci * 9 + k) * 4 + pp];
                        acc[2 * pp]     = fma2(v[k], W.x, acc[2 * pp]);
                        acc[2 * pp + 1] = fma2(v[k], W.y, acc[2 * pp + 1]);
                    }
                }
            }
#pragma unroll
            for (int p = 0; p < 8; p++) {
                float lo, hi;
                upk2(acc[p], lo, hi);
                lo = fmaxf(lo, 0.f);
                hi = fmaxf(hi, 0.f);
                s_h1[(2 * p) * 612 + hr * 34 + col + 1]     = pk2(lo, lo);
                s_h1[(2 * p + 1) * 612 + hr * 34 + col + 1] = pk2(hi, hi);
            }
        } else {
#pragma unroll
            for (int c = 0; c < 16; c++)
                s_h1[c * 612 + hr * 34 + col + 1] = 0ull;
        }
    }
    __syncthreads();

    // ---- conv2: 512 threads = 16 rows x 32 cols + fc partials ----
    {
        const int tx = tid & 31, ty = tid >> 5;
        ull acc2[4];
#pragma unroll
        for (int p = 0; p < 4; p++) acc2[p] = pk2(s_b2[2 * p], s_b2[2 * p + 1]);
#pragma unroll
        for (int ci = 0; ci < 16; ci++) {
            ull v[9];
#pragma unroll
            for (int dy = 0; dy < 3; dy++)
#pragma unroll
                for (int dx = 0; dx < 3; dx++)
                    v[dy * 3 + dx] = s_h1[ci * 612 + (ty + dy) * 34 + tx + dx];
#pragma unroll
            for (int k = 0; k < 9; k++) {
#pragma unroll
                for (int pp = 0; pp < 2; pp++) {
                    ulonglong2 W = c_w.w2[(ci * 9 + k) * 2 + pp];
                    acc2[2 * pp]     = fma2(v[k], W.x, acc2[2 * pp]);
                    acc2[2 * pp + 1] = fma2(v[k], W.y, acc2[2 * pp + 1]);
                }
            }
        }
        const int y = y0 + ty;
        float h[8];
#pragma unroll
        for (int p = 0; p < 4; p++) {
            float lo, hi;
            upk2(acc2[p], lo, hi);
            h[2 * p]     = fmaxf(lo, 0.f);
            h[2 * p + 1] = fmaxf(hi, 0.f);
        }
        float pr[4] = {0.f, 0.f, 0.f, 0.f};
#pragma unroll
        for (int c = 0; c < 8; c++) {
            int k = c * 1024 + y * 32 + tx;
#pragma unroll
            for (int j = 0; j < 4; j++)
                pr[j] = fmaf(h[c], __ldg(fcw + j * 8192 + k), pr[j]);
        }
#pragma unroll
        for (int off = 16; off > 0; off >>= 1)
#pragma unroll
            for (int j = 0; j < 4; j++)
                pr[j] += __shfl_down_sync(0xffffffffu, pr[j], off);
        if (tx == 0)
#pragma unroll
            for (int j = 0; j < 4; j++) swp[ty][j] = pr[j];
    }
    __syncthreads();
    if (tid < 4) {
        float s = 0.f;
#pragma unroll
        for (int wq = 0; wq < 16; wq++) s += swp[wq][tid];
        part[b * 8 + ck * 4 + tid] = s;
    }
}

// ---------------------------------------------------------------------------
// Y build: one thread per (img, pixel, channel-pair).
// ---------------------------------------------------------------------------
__global__ __launch_bounds__(256) void ybuild_kernel(
    const float* __restrict__ f2w, const float* __restrict__ f2b,
    const float* __restrict__ d1b, float* __restrict__ Y)
{
    const int idx  = blockIdx.x * 256 + threadIdx.x;
    const int px   = idx & 1023;
    const int pair = (idx >> 10) & 7;
    const int img  = idx >> 13;
    const int y = px >> 5, x = px & 31;
    const int pp = pair >> 1, half = pair & 1;

    ull acc = (img == 4) ? pk2(d1b[2 * pair], d1b[2 * pair + 1]) : pk2(0.f, 0.f);
#pragma unroll
    for (int ci = 0; ci < 8; ci++) {
#pragma unroll
        for (int dy = 0; dy < 3; dy++) {
            int gy = y + dy - 1;
            if ((unsigned)gy >= 32u) continue;
#pragma unroll
            for (int dx = 0; dx < 3; dx++) {
                int gx = x + dx - 1;
                if ((unsigned)gx >= 32u) continue;
                int k = ci * 1024 + gy * 32 + gx;
                float v = (img < 4) ? __ldg(f2w + (size_t)k * 4 + img) : __ldg(f2b + k);
                ulonglong2 W = c_w.wy[(ci * 9 + dy * 3 + dx) * 4 + pp];
                acc = fma2(pk2(v, v), half ? W.y : W.x, acc);
            }
        }
    }
    float lo, hi;
    upk2(acc, lo, hi);
    Y[img * 16384 + (2 * pair) * 1024 + px]     = lo;
    Y[img * 16384 + (2 * pair + 1) * 1024 + px] = hi;
}

// ---------------------------------------------------------------------------
// Quantum: 4 threads per batch element; each owns 4 of 16 output rows.
// ---------------------------------------------------------------------------
__global__ __launch_bounds__(128) void quantum_kernel(
    const float* __restrict__ part, const float* __restrict__ fcb,
    const float2* __restrict__ V, float* __restrict__ qout)
{
    __shared__ float2 sV[256];
    for (int i = threadIdx.x; i < 256; i += 128) sV[i] = V[i];
    __syncthreads();

    const int t = blockIdx.x * 128 + threadIdx.x;
    const int b = t >> 2, sub = t & 3;
    const int i0 = sub * 4;

    float c[4], s[4];
#pragma unroll
    for (int w = 0; w < 4; w++) {
        float ang = part[b * 8 + w] + part[b * 8 + 4 + w] + fcb[w];
        float half = ang * 0.5f;
        c[w] = cosf(half);
        s[w] = sinf(half);
    }

    float2 amp[16];
#pragma unroll
    for (int i = 0; i < 16; i++) {
        float m = ((i >> 3) & 1 ? s[0] : c[0]) * ((i >> 2) & 1 ? s[1] : c[1])
                * ((i >> 1) & 1 ? s[2] : c[2]) * ((i) & 1 ? s[3] : c[3]);
        int pc = __popc(i) & 3;
        amp[i] = (pc == 0) ? make_float2(m, 0.f)
               : (pc == 1) ? make_float2(0.f, -m)
               : (pc == 2) ? make_float2(-m, 0.f)
                           : make_float2(0.f, m);
    }

    float2 tr[4];
#pragma unroll
    for (int r = 0; r < 4; r++) tr[r] = make_float2(0.f, 0.f);
#pragma unroll
    for (int k = 0; k < 16; k++) {
        float2 a = amp[k];
#pragma unroll
        for (int r = 0; r < 4; r++) {
            float2 v = sV[(i0 + r) * 16 + k];
            tr[r].x = fmaf(v.x, a.x, fmaf(-v.y, a.y, tr[r].x));
            tr[r].y = fmaf(v.x, a.y, fmaf(v.y, a.x, tr[r].y));
        }
    }

    float ev[4] = {0.f, 0.f, 0.f, 0.f};
#pragma unroll
    for (int r = 0; r < 4; r++) {
        const int i = i0 + r;
        float p = tr[r].x * tr[r].x + tr[r].y * tr[r].y;
#pragma unroll
        for (int w = 0; w < 4; w++)
            ev[w] += (i & (1 << (3 - w))) ? -p : p;
    }
#pragma unroll
    for (int w = 0; w < 4; w++) {
        ev[w] += __shfl_xor_sync(0xffffffffu, ev[w], 1);
        ev[w] += __shfl_xor_sync(0xffffffffu, ev[w], 2);
    }
    if (sub == 0)
#pragma unroll
        for (int w = 0; w < 4; w++) qout[b * 4 + w] = ev[w];
}

// ---------------------------------------------------------------------------
// Fused output: Y tile in smem once; h3 stored DUPLICATED so the dconv2
// operands come from LDS.64 with zero movs; co2 rides a zero-padded pair.
// 8 passes x 2 batches x 256 threads.
// ---------------------------------------------------------------------------
#define YTILE 5440
__global__ __launch_bounds__(512) void fused_out_kernel(
    const float* __restrict__ q, const float* __restrict__ Y,
    const float* __restrict__ bias, float* __restrict__ out)
{
    extern __shared__ float smemf[];
    float* sY = smemf;                       // 5*YTILE floats
    ull*   sH = (ull*)(smemf + 5 * YTILE);   // 2*YTILE ull (dup)

    __shared__ ull s_wdp[144];
    __shared__ ull s_wd2[144];
    __shared__ float s_b[3];

    const int ck = blockIdx.x;
    const int y0 = ck * 8;
    const int b0 = blockIdx.y * 16;
    const int tid  = threadIdx.x;
    const int half = tid >> 8;
    const int htid = tid & 255;

    if (tid < 3) s_b[tid] = bias[tid];
    if (tid >= 16 && tid < 160) {
        int j = tid - 16;
        s_wdp[j] = c_w.wdp[j];
        s_wd2[j] = pk2(c_w.wds[j], 0.f);
    }

    if (tid < 340) {
        const int r = tid / 34, xc = tid - 34 * r;
        const int gy = y0 + r - 1, gx = xc - 1;
        const bool ok = ((unsigned)gy < 32u) && ((unsigned)gx < 32u);
        const int goff = gy * 32 + gx;
#pragma unroll 4
        for (int pl = 0; pl < 80; pl++)
            sY[pl * 340 + tid] = ok ? __ldg(Y + pl * 1024 + goff) : 0.f;
    }
    __syncthreads();

    const int tx = htid & 31, ty = htid >> 5;
    ull* sHh = sH + half * YTILE;
    const ull* sY2 = (const ull*)sY;

    for (int g = 0; g < 8; g++) {
        const int b = b0 + 2 * g + half;
        const float q0 = __ldg(q + b * 4 + 0), q1 = __ldg(q + b * 4 + 1);
        const float q2 = __ldg(q + b * 4 + 2), q3 = __ldg(q + b * 4 + 3);
        const ull Q0 = pk2(q0, q0), Q1 = pk2(q1, q1);
        const ull Q2 = pk2(q2, q2), Q3 = pk2(q3, q3);

        // combine + relu; write DUPLICATED pairs
        for (int i = htid; i < 2720; i += 256) {
            ull v = fma2(Q0, sY2[i],
                    fma2(Q1, sY2[2720 + i],
                    fma2(Q2, sY2[5440 + i],
                    fma2(Q3, sY2[8160 + i], sY2[10880 + i]))));
            float lo, hi;
            upk2(v, lo, hi);
            lo = fmaxf(lo, 0.f);
            hi = fmaxf(hi, 0.f);
            sHh[2 * i]     = pk2(lo, lo);
            sHh[2 * i + 1] = pk2(hi, hi);
        }
        __syncthreads();

        // dconv2 (16->3) + sigmoid: pure LDS.64 + fma2
        ull acc2  = pk2(s_b[0], s_b[1]);
        ull acc2b = pk2(s_b[2], 0.f);
#pragma unroll
        for (int ci = 0; ci < 16; ci++) {
            ull v[9];
#pragma unroll
            for (int dy = 0; dy < 3; dy++)
#pragma unroll
                for (int dx = 0; dx < 3; dx++)
                    v[dy * 3 + dx] = sHh[ci * 340 + (ty + dy) * 34 + tx + dx];
#pragma unroll
            for (int k = 0; k < 9; k++) {
                acc2  = fma2(v[k], s_wdp[ci * 9 + k], acc2);
                acc2b = fma2(v[k], s_wd2[ci * 9 + k], acc2b);
            }
        }
        float r0, r1, r2, junk;
        upk2(acc2, r0, r1);
        upk2(acc2b, r2, junk);
        float* outp = out + (size_t)b * 3 * 1024 + (y0 + ty) * 32 + tx;
        outp[0]    = __fdividef(1.f, 1.f + __expf(-r0));
        outp[1024] = __fdividef(1.f, 1.f + __expf(-r1));
        outp[2048] = __fdividef(1.f, 1.f + __expf(-r2));
        __syncthreads();
    }
}

// ---------------------------------------------------------------------------

extern "C" void kernel_launch(void* const* d_in, const int* in_sizes, int n_in,
                              void* d_out, int out_size)
{
    const float* x   = (const float*)d_in[0];
    const float* c1w = (const float*)d_in[1];
    const float* c1b = (const float*)d_in[2];
    const float* c2w = (const float*)d_in[3];
    const float* c2b = (const float*)d_in[4];
    const float* fcw = (const float*)d_in[5];
    const float* fcb = (const float*)d_in[6];
    const float* qw  = (const float*)d_in[7];
    const float* f2w = (const float*)d_in[8];
    const float* f2b = (const float*)d_in[9];
    const float* d1w = (const float*)d_in[10];
    const float* d1b = (const float*)d_in[11];
    const float* d2w = (const float*)d_in[12];
    const float* d2b = (const float*)d_in[13];
    float* out = (float*)d_out;

    float *part, *qv, *Y, *pk;
    float2* V;
    cudaGetSymbolAddress((void**)&part, g_part);
    cudaGetSymbolAddress((void**)&qv,   g_q);
    cudaGetSymbolAddress((void**)&Y,    g_Y);
    cudaGetSymbolAddress((void**)&V,    g_V);
    cudaGetSymbolAddress((void**)&pk,   g_pk);

    cudaFuncSetAttribute(conv12_kernel,
                         cudaFuncAttributeMaxDynamicSharedMemorySize,
                         (XDUP + H1DUP) * 8);
    cudaFuncSetAttribute(fused_out_kernel,
                         cudaFuncAttributeMaxDynamicSharedMemorySize,
                         5 * YTILE * 4 + 2 * YTILE * 8);

    setup_kernel<<<8, 256>>>(c1w, c2w, d1w, d2w, qw, V);
    cudaMemcpyToSymbolAsync(c_w, pk, sizeof(CW), 0, cudaMemcpyDeviceToDevice, 0);

    ybuild_kernel<<<160, 256>>>(f2w, f2b, d1b, Y);
    probe_kernel<<<1, 32>>>();
    conv12_kernel<<<dim3(2, BATCH), 512, (XDUP + H1DUP) * 8>>>(x, c1b, c2b, fcw, part);
    quantum_kernel<<<BATCH / 32, 128>>>(part, fcb, V, qv);
    fused_out_kernel<<<dim3(4, BATCH / 16), 512,
                       5 * YTILE * 4 + 2 * YTILE * 8>>>(qv, Y, d2b, out);
}

// round 14
// speedup vs baseline: 1.5740x; 1.5740x over previous
#include <cuda_runtime.h>
#include <math.h>

#define BATCH 2048
typedef unsigned long long ull;

// ---------------------------------------------------------------------------
// f32x2 packed helpers (sm_100+)
// ---------------------------------------------------------------------------
__device__ __forceinline__ ull pk2(float a, float b) {
    ull r;
    asm("mov.b64 %0, {%1, %2};" : "=l"(r) : "f"(a), "f"(b));
    return r;
}
__device__ __forceinline__ void upk2(ull v, float& a, float& b) {
    asm("mov.b64 {%0, %1}, %2;" : "=f"(a), "=f"(b) : "l"(v));
}
__device__ __forceinline__ ull fma2(ull a, ull b, ull c) {
    ull d;
    asm("fma.rn.f32x2 %0, %1, %2, %3;" : "=l"(d) : "l"(a), "l"(b), "l"(c));
    return d;
}

// ---------------------------------------------------------------------------
// Packed weight bank.
//   w1  : conv1 (co,co+1) pairs        [(ci*9+k)*4 + pp]
//   w2p : conv2 K-packed (ci2cp,2cp+1) [(cp*9+k)*8 + co]
//   wy  : dconv1 (co,co+1) pairs       [(ci*9+k)*4 + pp]
//   wdp2: dconv2 K-packed              [(cp*9+k)*3 + co]
// ---------------------------------------------------------------------------
struct CW {
    ulonglong2 w1[108];
    ull        w2p[576];
    ulonglong2 wy[288];
    ull        wdp2[216];
};
__device__ CW g_pk;
__constant__ CW c_w;

// Scratch
__device__ float g_part[BATCH * 8];
__device__ float g_q[BATCH * 4];
__device__ float g_Y[5 * 16 * 1024];
__device__ float2 g_V[256];

// ---------------------------------------------------------------------------
// Setup: repack weights; block 7 builds the fixed 16x16 entangling unitary.
// ---------------------------------------------------------------------------
__device__ __forceinline__ float2 cmul(float2 a, float2 b) {
    return make_float2(a.x * b.x - a.y * b.y, a.x * b.y + a.y * b.x);
}

__global__ __launch_bounds__(256) void setup_kernel(
    const float* __restrict__ c1w, const float* __restrict__ c2w,
    const float* __restrict__ d1w, const float* __restrict__ d2w,
    const float* __restrict__ qw, float2* __restrict__ V)
{
    if (blockIdx.x == 7) {
        const int tid = threadIdx.x;
        if (tid >= 16) return;
        float2 st[16];
#pragma unroll
        for (int i = 0; i < 16; i++) st[i] = make_float2(0.f, 0.f);
        st[tid].x = 1.f;
#pragma unroll
        for (int l = 0; l < 3; l++) {
#pragma unroll
            for (int w = 0; w < 4; w++) {
                float phi = qw[(l * 4 + w) * 3 + 0];
                float th  = qw[(l * 4 + w) * 3 + 1];
                float om  = qw[(l * 4 + w) * 3 + 2];
                float ct = cosf(th * 0.5f), stt = sinf(th * 0.5f);
                float a = (phi + om) * 0.5f, d = (phi - om) * 0.5f;
                float ca = cosf(a), sa = sinf(a), cd = cosf(d), sd = sinf(d);
                float2 U00 = make_float2(ct * ca, -ct * sa);
                float2 U01 = make_float2(-stt * cd, -stt * sd);
                float2 U10 = make_float2(stt * cd, -stt * sd);
                float2 U11 = make_float2(ct * ca, ct * sa);
                const int bit = 1 << (3 - w);
#pragma unroll
                for (int i = 0; i < 16; i++) {
                    if (i & bit) continue;
                    float2 a0 = st[i], a1 = st[i | bit];
                    float2 n0 = cmul(U00, a0), n1 = cmul(U10, a0);
                    float2 m0 = cmul(U01, a1), m1 = cmul(U11, a1);
                    st[i]       = make_float2(n0.x + m0.x, n0.y + m0.y);
                    st[i | bit] = make_float2(n1.x + m1.x, n1.y + m1.y);
                }
            }
            const int r = (l % 3) + 1;
#pragma unroll
            for (int w = 0; w < 4; w++) {
                const int cb = 1 << (3 - w);
                const int tb = 1 << (3 - ((w + r) & 3));
#pragma unroll
                for (int i = 0; i < 16; i++) {
                    if ((i & cb) && !(i & tb)) {
                        float2 tmp = st[i]; st[i] = st[i | tb]; st[i | tb] = tmp;
                    }
                }
            }
        }
#pragma unroll
        for (int i = 0; i < 16; i++) V[i * 16 + tid] = st[i];
        return;
    }

    int i = blockIdx.x * 256 + threadIdx.x;
    float* pkf = (float*)&g_pk;
    // float offsets: w1 @0, w2p @432, wy @1584, wdp2 @2736
    if (i < 216) {                                  // conv1: 3*9*8 pairs
        int p = i & 7, t = i >> 3;
        int k = t % 9, ci = t / 9;
        pkf[2 * i]     = c1w[(2 * p) * 27 + ci * 9 + k];
        pkf[2 * i + 1] = c1w[(2 * p + 1) * 27 + ci * 9 + k];
    } else if (i < 792) {                           // conv2 K-packed: 576 ull
        int j = i - 216;
        int co = j & 7, t = j >> 3;
        int k = t % 9, cp = t / 9;
        pkf[432 + 2 * j]     = c2w[co * 144 + (2 * cp) * 9 + k];
        pkf[432 + 2 * j + 1] = c2w[co * 144 + (2 * cp + 1) * 9 + k];
    } else if (i < 1368) {                          // dconv1: 8*9*8 pairs
        int j = i - 792;
        int p = j & 7, t = j >> 3;
        int k = t % 9, ci = t / 9;
        pkf[1584 + 2 * j]     = d1w[(2 * p) * 72 + ci * 9 + k];
        pkf[1584 + 2 * j + 1] = d1w[(2 * p + 1) * 72 + ci * 9 + k];
    } else if (i < 1584) {                          // dconv2 K-packed: 216 ull
        int j = i - 1368;
        int co = j % 3, t = j / 3;
        int k = t % 9, cp = t / 9;
        pkf[2736 + 2 * j]     = d2w[co * 144 + (2 * cp) * 9 + k];
        pkf[2736 + 2 * j + 1] = d2w[co * 144 + (2 * cp + 1) * 9 + k];
    }
}

// ---------------------------------------------------------------------------
// No-op probe: keeps conv12 in the ncu capture window.
// ---------------------------------------------------------------------------
__global__ void probe_kernel() {}

// ---------------------------------------------------------------------------
// Fused conv1+conv2+fc: 16-row chunks, 512 threads.
// h1 stored as 8 channel-pair planes of float2 (ull) -> conv2 taps are
// single aligned LDS.64, zero duplication movs, K packed into fma2 lanes.
// Dynamic smem: x fp32 (8160 B) + h1 pairs (39168 B) = 47328 B; 3 blocks/SM.
// ---------------------------------------------------------------------------
#define XSZ2 2040    // 3*20*34 floats
#define H1P  612     // per-plane ull (18*34)
__global__ __launch_bounds__(512) void conv12_kernel(
    const float* __restrict__ in, const float* __restrict__ b1,
    const float* __restrict__ b2, const float* __restrict__ fcw,
    float* __restrict__ part)
{
    extern __shared__ char dsm[];
    float* s_x  = (float*)dsm;                // [ci][r<20][c<34]
    ull*   s_h1 = (ull*)(dsm + XSZ2 * 4);     // [cp<8][r<18][c<34]
    __shared__ float s_b1[16];
    __shared__ float s_b2[8];
    __shared__ float swp[16][4];

    const int b  = blockIdx.y;
    const int ck = blockIdx.x;
    const int y0 = ck * 16;
    const int tid = threadIdx.x;

    if (tid < 16) s_b1[tid] = b1[tid];
    else if (tid < 24) s_b2[tid - 16] = b2[tid - 16];

    const float* inb = in + (size_t)b * 3 * 1024;
    for (int i = tid; i < XSZ2; i += 512) {
        int c = i / 680, rem = i - c * 680;
        int r = rem / 34, xc = rem - r * 34;
        int gy = y0 - 2 + r, gx = xc - 1;
        float v = 0.f;
        if ((unsigned)gy < 32u && (unsigned)gx < 32u) v = inb[c * 1024 + gy * 32 + gx];
        s_x[i] = v;
    }
    // zero h1 col halo (8 planes x 18 rows x {0,33})
    if (tid < 36) {
        int hr = tid >> 1, xc = (tid & 1) ? 33 : 0;
#pragma unroll
        for (int p = 0; p < 8; p++) s_h1[p * H1P + hr * 34 + xc] = 0ull;
    }
    __syncthreads();

    // ---- conv1: 576 items (18 rows x 32 cols), strided over 512 threads ----
    for (int it = tid; it < 576; it += 512) {
        const int hr = it >> 5, col = it & 31;
        const int gy = y0 - 1 + hr;
        if ((unsigned)gy < 32u) {
            ull acc[8];
#pragma unroll
            for (int p = 0; p < 8; p++) acc[p] = pk2(s_b1[2 * p], s_b1[2 * p + 1]);
#pragma unroll
            for (int ci = 0; ci < 3; ci++) {
                float v[9];
#pragma unroll
                for (int dy = 0; dy < 3; dy++)
#pragma unroll
                    for (int dx = 0; dx < 3; dx++)
                        v[dy * 3 + dx] = s_x[ci * 680 + (hr + dy) * 34 + col + dx];
#pragma unroll
                for (int k = 0; k < 9; k++) {
                    ull vv = pk2(v[k], v[k]);
#pragma unroll
                    for (int pp = 0; pp < 4; pp++) {
                        ulonglong2 W = c_w.w1[(ci * 9 + k) * 4 + pp];
                        acc[2 * pp]     = fma2(vv, W.x, acc[2 * pp]);
                        acc[2 * pp + 1] = fma2(vv, W.y, acc[2 * pp + 1]);
                    }
                }
            }
#pragma unroll
            for (int p = 0; p < 8; p++) {
                float lo, hi;
                upk2(acc[p], lo, hi);
                lo = fmaxf(lo, 0.f);
                hi = fmaxf(hi, 0.f);
                s_h1[p * H1P + hr * 34 + col + 1] = pk2(lo, hi);
            }
        } else {
#pragma unroll
            for (int p = 0; p < 8; p++)
                s_h1[p * H1P + hr * 34 + col + 1] = 0ull;
        }
    }
    __syncthreads();

    // ---- conv2 K-packed: 512 threads = 16 rows x 32 cols + fc partials ----
    {
        const int tx = tid & 31, ty = tid >> 5;
        ull acc[8];
#pragma unroll
        for (int co = 0; co < 8; co++) acc[co] = pk2(s_b2[co], 0.f);
#pragma unroll
        for (int cp = 0; cp < 8; cp++) {
            ull v[9];
#pragma unroll
            for (int dy = 0; dy < 3; dy++)
#pragma unroll
                for (int dx = 0; dx < 3; dx++)
                    v[dy * 3 + dx] = s_h1[cp * H1P + (ty + dy) * 34 + tx + dx];
#pragma unroll
            for (int k = 0; k < 9; k++) {
#pragma unroll
                for (int co = 0; co < 8; co++)
                    acc[co] = fma2(v[k], c_w.w2p[(cp * 9 + k) * 8 + co], acc[co]);
            }
        }
        const int y = y0 + ty;
        float h[8];
#pragma unroll
        for (int co = 0; co < 8; co++) {
            float lo, hi;
            upk2(acc[co], lo, hi);
            h[co] = fmaxf(lo + hi, 0.f);
        }
        float pr[4] = {0.f, 0.f, 0.f, 0.f};
#pragma unroll
        for (int c = 0; c < 8; c++) {
            int k = c * 1024 + y * 32 + tx;
#pragma unroll
            for (int j = 0; j < 4; j++)
                pr[j] = fmaf(h[c], __ldg(fcw + j * 8192 + k), pr[j]);
        }
#pragma unroll
        for (int off = 16; off > 0; off >>= 1)
#pragma unroll
            for (int j = 0; j < 4; j++)
                pr[j] += __shfl_down_sync(0xffffffffu, pr[j], off);
        if (tx == 0)
#pragma unroll
            for (int j = 0; j < 4; j++) swp[ty][j] = pr[j];
    }
    __syncthreads();
    if (tid < 4) {
        float s = 0.f;
#pragma unroll
        for (int wq = 0; wq < 16; wq++) s += swp[wq][tid];
        part[b * 8 + ck * 4 + tid] = s;
    }
}

// ---------------------------------------------------------------------------
// Y build: one thread per (img, pixel, channel-pair).
// ---------------------------------------------------------------------------
__global__ __launch_bounds__(256) void ybuild_kernel(
    const float* __restrict__ f2w, const float* __restrict__ f2b,
    const float* __restrict__ d1b, float* __restrict__ Y)
{
    const int idx  = blockIdx.x * 256 + threadIdx.x;
    const int px   = idx & 1023;
    const int pair = (idx >> 10) & 7;
    const int img  = idx >> 13;
    const int y = px >> 5, x = px & 31;
    const int pp = pair >> 1, half = pair & 1;

    ull acc = (img == 4) ? pk2(d1b[2 * pair], d1b[2 * pair + 1]) : pk2(0.f, 0.f);
#pragma unroll
    for (int ci = 0; ci < 8; ci++) {
#pragma unroll
        for (int dy = 0; dy < 3; dy++) {
            int gy = y + dy - 1;
            if ((unsigned)gy >= 32u) continue;
#pragma unroll
            for (int dx = 0; dx < 3; dx++) {
                int gx = x + dx - 1;
                if ((unsigned)gx >= 32u) continue;
                int k = ci * 1024 + gy * 32 + gx;
                float v = (img < 4) ? __ldg(f2w + (size_t)k * 4 + img) : __ldg(f2b + k);
                ulonglong2 W = c_w.wy[(ci * 9 + dy * 3 + dx) * 4 + pp];
                acc = fma2(pk2(v, v), half ? W.y : W.x, acc);
            }
        }
    }
    float lo, hi;
    upk2(acc, lo, hi);
    Y[img * 16384 + (2 * pair) * 1024 + px]     = lo;
    Y[img * 16384 + (2 * pair + 1) * 1024 + px] = hi;
}

// ---------------------------------------------------------------------------
// Quantum: 4 threads per batch element; each owns 4 of 16 output rows.
// ---------------------------------------------------------------------------
__global__ __launch_bounds__(128) void quantum_kernel(
    const float* __restrict__ part, const float* __restrict__ fcb,
    const float2* __restrict__ V, float* __restrict__ qout)
{
    __shared__ float2 sV[256];
    for (int i = threadIdx.x; i < 256; i += 128) sV[i] = V[i];
    __syncthreads();

    const int t = blockIdx.x * 128 + threadIdx.x;
    const int b = t >> 2, sub = t & 3;
    const int i0 = sub * 4;

    float c[4], s[4];
#pragma unroll
    for (int w = 0; w < 4; w++) {
        float ang = part[b * 8 + w] + part[b * 8 + 4 + w] + fcb[w];
        float half = ang * 0.5f;
        c[w] = cosf(half);
        s[w] = sinf(half);
    }

    float2 amp[16];
#pragma unroll
    for (int i = 0; i < 16; i++) {
        float m = ((i >> 3) & 1 ? s[0] : c[0]) * ((i >> 2) & 1 ? s[1] : c[1])
                * ((i >> 1) & 1 ? s[2] : c[2]) * ((i) & 1 ? s[3] : c[3]);
        int pc = __popc(i) & 3;
        amp[i] = (pc == 0) ? make_float2(m, 0.f)
               : (pc == 1) ? make_float2(0.f, -m)
               : (pc == 2) ? make_float2(-m, 0.f)
                           : make_float2(0.f, m);
    }

    float2 tr[4];
#pragma unroll
    for (int r = 0; r < 4; r++) tr[r] = make_float2(0.f, 0.f);
#pragma unroll
    for (int k = 0; k < 16; k++) {
        float2 a = amp[k];
#pragma unroll
        for (int r = 0; r < 4; r++) {
            float2 v = sV[(i0 + r) * 16 + k];
            tr[r].x = fmaf(v.x, a.x, fmaf(-v.y, a.y, tr[r].x));
            tr[r].y = fmaf(v.x, a.y, fmaf(v.y, a.x, tr[r].y));
        }
    }

    float ev[4] = {0.f, 0.f, 0.f, 0.f};
#pragma unroll
    for (int r = 0; r < 4; r++) {
        const int i = i0 + r;
        float p = tr[r].x * tr[r].x + tr[r].y * tr[r].y;
#pragma unroll
        for (int w = 0; w < 4; w++)
            ev[w] += (i & (1 << (3 - w))) ? -p : p;
    }
#pragma unroll
    for (int w = 0; w < 4; w++) {
        ev[w] += __shfl_xor_sync(0xffffffffu, ev[w], 1);
        ev[w] += __shfl_xor_sync(0xffffffffu, ev[w], 2);
    }
    if (sub == 0)
#pragma unroll
        for (int w = 0; w < 4; w++) qout[b * 4 + w] = ev[w];
}

// ---------------------------------------------------------------------------
// Fused output: sY and sH in channel-pair-plane float2 layout; K-packed
// dconv2 (216 fma2/px, pure LDS.64 taps). 8 passes x 2 batches x 256 thr.
// ---------------------------------------------------------------------------
#define FP 340    // per (img,cp) plane in ull (10 rows x 34 cols)
__global__ __launch_bounds__(512) void fused_out_kernel(
    const float* __restrict__ q, const float* __restrict__ Y,
    const float* __restrict__ bias, float* __restrict__ out)
{
    extern __shared__ ull usm[];
    ull* sY = usm;                 // [img<5][cp<8][px<340]
    ull* sH = usm + 5 * 8 * FP;    // [half<2][cp<8][px<340]

    __shared__ float s_b[3];

    const int ck = blockIdx.x;
    const int y0 = ck * 8;
    const int b0 = blockIdx.y * 16;
    const int tid  = threadIdx.x;
    const int half = tid >> 8;
    const int htid = tid & 255;

    if (tid < 3) s_b[tid] = bias[tid];

    if (tid < 340) {
        const int r = tid / 34, xc = tid - 34 * r;
        const int gy = y0 + r - 1, gx = xc - 1;
        const bool ok = ((unsigned)gy < 32u) && ((unsigned)gx < 32u);
        const int goff = gy * 32 + gx;
#pragma unroll
        for (int img = 0; img < 5; img++)
#pragma unroll
            for (int cp = 0; cp < 8; cp++) {
                float a = 0.f, bb = 0.f;
                if (ok) {
                    a  = __ldg(Y + img * 16384 + (2 * cp) * 1024 + goff);
                    bb = __ldg(Y + img * 16384 + (2 * cp + 1) * 1024 + goff);
                }
                sY[(img * 8 + cp) * FP + tid] = pk2(a, bb);
            }
    }
    __syncthreads();

    const int tx = htid & 31, ty = htid >> 5;
    ull* sHh = sH + half * 8 * FP;

    for (int g = 0; g < 8; g++) {
        const int b = b0 + 2 * g + half;
        const float q0 = __ldg(q + b * 4 + 0), q1 = __ldg(q + b * 4 + 1);
        const float q2 = __ldg(q + b * 4 + 2), q3 = __ldg(q + b * 4 + 3);
        const ull Q0 = pk2(q0, q0), Q1 = pk2(q1, q1);
        const ull Q2 = pk2(q2, q2), Q3 = pk2(q3, q3);

        // combine + relu over pair planes (i = cp*FP + px)
        for (int i = htid; i < 8 * FP; i += 256) {
            ull v = fma2(Q0, sY[i],
                    fma2(Q1, sY[8 * FP + i],
                    fma2(Q2, sY[16 * FP + i],
                    fma2(Q3, sY[24 * FP + i], sY[32 * FP + i]))));
            float lo, hi;
            upk2(v, lo, hi);
            sHh[i] = pk2(fmaxf(lo, 0.f), fmaxf(hi, 0.f));
        }
        __syncthreads();

        // dconv2 K-packed (16->3) + sigmoid
        ull acc[3];
#pragma unroll
        for (int co = 0; co < 3; co++) acc[co] = pk2(s_b[co], 0.f);
#pragma unroll
        for (int cp = 0; cp < 8; cp++) {
            ull v[9];
#pragma unroll
            for (int dy = 0; dy < 3; dy++)
#pragma unroll
                for (int dx = 0; dx < 3; dx++)
                    v[dy * 3 + dx] = sHh[cp * FP + (ty + dy) * 34 + tx + dx];
#pragma unroll
            for (int k = 0; k < 9; k++) {
#pragma unroll
                for (int co = 0; co < 3; co++)
                    acc[co] = fma2(v[k], c_w.wdp2[(cp * 9 + k) * 3 + co], acc[co]);
            }
        }
        float* outp = out + (size_t)b * 3 * 1024 + (y0 + ty) * 32 + tx;
#pragma unroll
        for (int co = 0; co < 3; co++) {
            float lo, hi;
            upk2(acc[co], lo, hi);
            outp[co * 1024] = __fdividef(1.f, 1.f + __expf(-(lo + hi)));
        }
        __syncthreads();
    }
}

// ---------------------------------------------------------------------------

extern "C" void kernel_launch(void* const* d_in, const int* in_sizes, int n_in,
                              void* d_out, int out_size)
{
    const float* x   = (const float*)d_in[0];
    const float* c1w = (const float*)d_in[1];
    const float* c1b = (const float*)d_in[2];
    const float* c2w = (const float*)d_in[3];
    const float* c2b = (const float*)d_in[4];
    const float* fcw = (const float*)d_in[5];
    const float* fcb = (const float*)d_in[6];
    const float* qw  = (const float*)d_in[7];
    const float* f2w = (const float*)d_in[8];
    const float* f2b = (const float*)d_in[9];
    const float* d1w = (const float*)d_in[10];
    const float* d1b = (const float*)d_in[11];
    const float* d2w = (const float*)d_in[12];
    const float* d2b = (const float*)d_in[13];
    float* out = (float*)d_out;

    float *part, *qv, *Y, *pk;
    float2* V;
    cudaGetSymbolAddress((void**)&part, g_part);
    cudaGetSymbolAddress((void**)&qv,   g_q);
    cudaGetSymbolAddress((void**)&Y,    g_Y);
    cudaGetSymbolAddress((void**)&V,    g_V);
    cudaGetSymbolAddress((void**)&pk,   g_pk);

    const int conv12_smem = XSZ2 * 4 + 8 * H1P * 8;       // 47328 B
    const int fo_smem     = (5 + 2) * 8 * FP * 8;         // 152320 B

    cudaFuncSetAttribute(conv12_kernel,
                         cudaFuncAttributeMaxDynamicSharedMemorySize, conv12_smem);
    cudaFuncSetAttribute(fused_out_kernel,
                         cudaFuncAttributeMaxDynamicSharedMemorySize, fo_smem);

    setup_kernel<<<8, 256>>>(c1w, c2w, d1w, d2w, qw, V);
    cudaMemcpyToSymbolAsync(c_w, pk, sizeof(CW), 0, cudaMemcpyDeviceToDevice, 0);

    ybuild_kernel<<<160, 256>>>(f2w, f2b, d1b, Y);
    probe_kernel<<<1, 32>>>();
    conv12_kernel<<<dim3(2, BATCH), 512, conv12_smem>>>(x, c1b, c2b, fcw, part);
    quantum_kernel<<<BATCH / 32, 128>>>(part, fcb, V, qv);
    fused_out_kernel<<<dim3(4, BATCH / 16), 512, fo_smem>>>(qv, Y, d2b, out);
}

// round 15
// speedup vs baseline: 1.6143x; 1.0256x over previous
#include <cuda_runtime.h>
#include <math.h>

#define BATCH 2048
typedef unsigned long long ull;

// ---------------------------------------------------------------------------
// f32x2 packed helpers (sm_100+)
// ---------------------------------------------------------------------------
__device__ __forceinline__ ull pk2(float a, float b) {
    ull r;
    asm("mov.b64 %0, {%1, %2};" : "=l"(r) : "f"(a), "f"(b));
    return r;
}
__device__ __forceinline__ void upk2(ull v, float& a, float& b) {
    asm("mov.b64 {%0, %1}, %2;" : "=f"(a), "=f"(b) : "l"(v));
}
__device__ __forceinline__ ull fma2(ull a, ull b, ull c) {
    ull d;
    asm("fma.rn.f32x2 %0, %1, %2, %3;" : "=l"(d) : "l"(a), "l"(b), "l"(c));
    return d;
}

// ---------------------------------------------------------------------------
// Packed weight bank.
//   w1  : conv1 (co,co+1) pairs        [(ci*9+k)*4 + pp]
//   w2p : conv2 K-packed (ci2cp,2cp+1) [(cp*9+k)*8 + co]
//   wy  : dconv1 (co,co+1) pairs       [(ci*9+k)*4 + pp]
//   wdp2: dconv2 K-packed              [(cp*9+k)*3 + co]
// ---------------------------------------------------------------------------
struct CW {
    ulonglong2 w1[108];
    ull        w2p[576];
    ulonglong2 wy[288];
    ull        wdp2[216];
};
__device__ CW g_pk;
__constant__ CW c_w;

// Scratch
__device__ float g_part[BATCH * 8];
__device__ float g_q[BATCH * 4];
__device__ float g_Y[5 * 16 * 1024];
__device__ float2 g_V[256];

// ---------------------------------------------------------------------------
// Setup: repack weights; block 7 builds the fixed 16x16 entangling unitary.
// ---------------------------------------------------------------------------
__device__ __forceinline__ float2 cmul(float2 a, float2 b) {
    return make_float2(a.x * b.x - a.y * b.y, a.x * b.y + a.y * b.x);
}

__global__ __launch_bounds__(256) void setup_kernel(
    const float* __restrict__ c1w, const float* __restrict__ c2w,
    const float* __restrict__ d1w, const float* __restrict__ d2w,
    const float* __restrict__ qw, float2* __restrict__ V)
{
    if (blockIdx.x == 7) {
        const int tid = threadIdx.x;
        if (tid >= 16) return;
        float2 st[16];
#pragma unroll
        for (int i = 0; i < 16; i++) st[i] = make_float2(0.f, 0.f);
        st[tid].x = 1.f;
#pragma unroll
        for (int l = 0; l < 3; l++) {
#pragma unroll
            for (int w = 0; w < 4; w++) {
                float phi = qw[(l * 4 + w) * 3 + 0];
                float th  = qw[(l * 4 + w) * 3 + 1];
                float om  = qw[(l * 4 + w) * 3 + 2];
                float ct = cosf(th * 0.5f), stt = sinf(th * 0.5f);
                float a = (phi + om) * 0.5f, d = (phi - om) * 0.5f;
                float ca = cosf(a), sa = sinf(a), cd = cosf(d), sd = sinf(d);
                float2 U00 = make_float2(ct * ca, -ct * sa);
                float2 U01 = make_float2(-stt * cd, -stt * sd);
                float2 U10 = make_float2(stt * cd, -stt * sd);
                float2 U11 = make_float2(ct * ca, ct * sa);
                const int bit = 1 << (3 - w);
#pragma unroll
                for (int i = 0; i < 16; i++) {
                    if (i & bit) continue;
                    float2 a0 = st[i], a1 = st[i | bit];
                    float2 n0 = cmul(U00, a0), n1 = cmul(U10, a0);
                    float2 m0 = cmul(U01, a1), m1 = cmul(U11, a1);
                    st[i]       = make_float2(n0.x + m0.x, n0.y + m0.y);
                    st[i | bit] = make_float2(n1.x + m1.x, n1.y + m1.y);
                }
            }
            const int r = (l % 3) + 1;
#pragma unroll
            for (int w = 0; w < 4; w++) {
                const int cb = 1 << (3 - w);
                const int tb = 1 << (3 - ((w + r) & 3));
#pragma unroll
                for (int i = 0; i < 16; i++) {
                    if ((i & cb) && !(i & tb)) {
                        float2 tmp = st[i]; st[i] = st[i | tb]; st[i | tb] = tmp;
                    }
                }
            }
        }
#pragma unroll
        for (int i = 0; i < 16; i++) V[i * 16 + tid] = st[i];
        return;
    }

    int i = blockIdx.x * 256 + threadIdx.x;
    float* pkf = (float*)&g_pk;
    // float offsets: w1 @0, w2p @432, wy @1584, wdp2 @2736
    if (i < 216) {                                  // conv1: 3*9*8 pairs
        int p = i & 7, t = i >> 3;
        int k = t % 9, ci = t / 9;
        pkf[2 * i]     = c1w[(2 * p) * 27 + ci * 9 + k];
        pkf[2 * i + 1] = c1w[(2 * p + 1) * 27 + ci * 9 + k];
    } else if (i < 792) {                           // conv2 K-packed: 576 ull
        int j = i - 216;
        int co = j & 7, t = j >> 3;
        int k = t % 9, cp = t / 9;
        pkf[432 + 2 * j]     = c2w[co * 144 + (2 * cp) * 9 + k];
        pkf[432 + 2 * j + 1] = c2w[co * 144 + (2 * cp + 1) * 9 + k];
    } else if (i < 1368) {                          // dconv1: 8*9*8 pairs
        int j = i - 792;
        int p = j & 7, t = j >> 3;
        int k = t % 9, ci = t / 9;
        pkf[1584 + 2 * j]     = d1w[(2 * p) * 72 + ci * 9 + k];
        pkf[1584 + 2 * j + 1] = d1w[(2 * p + 1) * 72 + ci * 9 + k];
    } else if (i < 1584) {                          // dconv2 K-packed: 216 ull
        int j = i - 1368;
        int co = j % 3, t = j / 3;
        int k = t % 9, cp = t / 9;
        pkf[2736 + 2 * j]     = d2w[co * 144 + (2 * cp) * 9 + k];
        pkf[2736 + 2 * j + 1] = d2w[co * 144 + (2 * cp + 1) * 9 + k];
    }
}

// ---------------------------------------------------------------------------
// No-op probe: keeps conv12 in the ncu capture window.
// ---------------------------------------------------------------------------
__global__ void probe_kernel() {}

// ---------------------------------------------------------------------------
// Fused conv1+conv2+fc: 16-row chunks, 576 threads.
//   conv1: 576 threads = 18 h1-rows x 32 cols, exactly ONE item each (no tail)
//   conv2: threads 0..511 = 16 rows x 32 cols, K-packed, + fc partials
// h1 stored as 8 channel-pair planes of float2 (ull) -> conv2 taps are
// single aligned LDS.64, zero duplication movs, K packed into fma2 lanes.
// ---------------------------------------------------------------------------
#define XSZ2 2040    // 3*20*34 floats
#define H1P  612     // per-plane ull (18*34)
__global__ __launch_bounds__(576) void conv12_kernel(
    const float* __restrict__ in, const float* __restrict__ b1,
    const float* __restrict__ b2, const float* __restrict__ fcw,
    float* __restrict__ part)
{
    extern __shared__ char dsm[];
    float* s_x  = (float*)dsm;                // [ci][r<20][c<34]
    ull*   s_h1 = (ull*)(dsm + XSZ2 * 4);     // [cp<8][r<18][c<34]
    __shared__ float s_b1[16];
    __shared__ float s_b2[8];
    __shared__ float swp[16][4];

    const int b  = blockIdx.y;
    const int ck = blockIdx.x;
    const int y0 = ck * 16;
    const int tid = threadIdx.x;

    if (tid < 16) s_b1[tid] = b1[tid];
    else if (tid < 24) s_b2[tid - 16] = b2[tid - 16];

    const float* inb = in + (size_t)b * 3 * 1024;
    for (int i = tid; i < XSZ2; i += 576) {
        int c = i / 680, rem = i - c * 680;
        int r = rem / 34, xc = rem - r * 34;
        int gy = y0 - 2 + r, gx = xc - 1;
        float v = 0.f;
        if ((unsigned)gy < 32u && (unsigned)gx < 32u) v = inb[c * 1024 + gy * 32 + gx];
        s_x[i] = v;
    }
    // zero h1 col halo (8 planes x 18 rows x {0,33})
    if (tid < 36) {
        int hr = tid >> 1, xc = (tid & 1) ? 33 : 0;
#pragma unroll
        for (int p = 0; p < 8; p++) s_h1[p * H1P + hr * 34 + xc] = 0ull;
    }
    __syncthreads();

    // ---- conv1: exactly one item per thread (18 rows x 32 cols) ----
    {
        const int hr = tid >> 5, col = tid & 31;
        const int gy = y0 - 1 + hr;
        if ((unsigned)gy < 32u) {
            ull acc[8];
#pragma unroll
            for (int p = 0; p < 8; p++) acc[p] = pk2(s_b1[2 * p], s_b1[2 * p + 1]);
#pragma unroll
            for (int ci = 0; ci < 3; ci++) {
                float v[9];
#pragma unroll
                for (int dy = 0; dy < 3; dy++)
#pragma unroll
                    for (int dx = 0; dx < 3; dx++)
                        v[dy * 3 + dx] = s_x[ci * 680 + (hr + dy) * 34 + col + dx];
#pragma unroll
                for (int k = 0; k < 9; k++) {
                    ull vv = pk2(v[k], v[k]);
#pragma unroll
                    for (int pp = 0; pp < 4; pp++) {
                        ulonglong2 W = c_w.w1[(ci * 9 + k) * 4 + pp];
                        acc[2 * pp]     = fma2(vv, W.x, acc[2 * pp]);
                        acc[2 * pp + 1] = fma2(vv, W.y, acc[2 * pp + 1]);
                    }
                }
            }
#pragma unroll
            for (int p = 0; p < 8; p++) {
                float lo, hi;
                upk2(acc[p], lo, hi);
                lo = fmaxf(lo, 0.f);
                hi = fmaxf(hi, 0.f);
                s_h1[p * H1P + hr * 34 + col + 1] = pk2(lo, hi);
            }
        } else {
#pragma unroll
            for (int p = 0; p < 8; p++)
                s_h1[p * H1P + hr * 34 + col + 1] = 0ull;
        }
    }
    __syncthreads();

    // ---- conv2 K-packed: threads 0..511 = 16 rows x 32 cols + fc partials ----
    if (tid < 512) {
        const int tx = tid & 31, ty = tid >> 5;
        ull acc[8];
#pragma unroll
        for (int co = 0; co < 8; co++) acc[co] = pk2(s_b2[co], 0.f);
#pragma unroll
        for (int cp = 0; cp < 8; cp++) {
            ull v[9];
#pragma unroll
            for (int dy = 0; dy < 3; dy++)
#pragma unroll
                for (int dx = 0; dx < 3; dx++)
                    v[dy * 3 + dx] = s_h1[cp * H1P + (ty + dy) * 34 + tx + dx];
#pragma unroll
            for (int k = 0; k < 9; k++) {
#pragma unroll
                for (int co = 0; co < 8; co++)
                    acc[co] = fma2(v[k], c_w.w2p[(cp * 9 + k) * 8 + co], acc[co]);
            }
        }
        const int y = y0 + ty;
        float h[8];
#pragma unroll
        for (int co = 0; co < 8; co++) {
            float lo, hi;
            upk2(acc[co], lo, hi);
            h[co] = fmaxf(lo + hi, 0.f);
        }
        float pr[4] = {0.f, 0.f, 0.f, 0.f};
#pragma unroll
        for (int c = 0; c < 8; c++) {
            int k = c * 1024 + y * 32 + tx;
#pragma unroll
            for (int j = 0; j < 4; j++)
                pr[j] = fmaf(h[c], __ldg(fcw + j * 8192 + k), pr[j]);
        }
#pragma unroll
        for (int off = 16; off > 0; off >>= 1)
#pragma unroll
            for (int j = 0; j < 4; j++)
                pr[j] += __shfl_down_sync(0xffffffffu, pr[j], off);
        if (tx == 0)
#pragma unroll
            for (int j = 0; j < 4; j++) swp[ty][j] = pr[j];
    }
    __syncthreads();
    if (tid < 4) {
        float s = 0.f;
#pragma unroll
        for (int wq = 0; wq < 16; wq++) s += swp[wq][tid];
        part[b * 8 + ck * 4 + tid] = s;
    }
}

// ---------------------------------------------------------------------------
// Y build: one thread per (img, pixel, channel-pair).
// ---------------------------------------------------------------------------
__global__ __launch_bounds__(256) void ybuild_kernel(
    const float* __restrict__ f2w, const float* __restrict__ f2b,
    const float* __restrict__ d1b, float* __restrict__ Y)
{
    const int idx  = blockIdx.x * 256 + threadIdx.x;
    const int px   = idx & 1023;
    const int pair = (idx >> 10) & 7;
    const int img  = idx >> 13;
    const int y = px >> 5, x = px & 31;
    const int pp = pair >> 1, half = pair & 1;

    ull acc = (img == 4) ? pk2(d1b[2 * pair], d1b[2 * pair + 1]) : pk2(0.f, 0.f);
#pragma unroll
    for (int ci = 0; ci < 8; ci++) {
#pragma unroll
        for (int dy = 0; dy < 3; dy++) {
            int gy = y + dy - 1;
            if ((unsigned)gy >= 32u) continue;
#pragma unroll
            for (int dx = 0; dx < 3; dx++) {
                int gx = x + dx - 1;
                if ((unsigned)gx >= 32u) continue;
                int k = ci * 1024 + gy * 32 + gx;
                float v = (img < 4) ? __ldg(f2w + (size_t)k * 4 + img) : __ldg(f2b + k);
                ulonglong2 W = c_w.wy[(ci * 9 + dy * 3 + dx) * 4 + pp];
                acc = fma2(pk2(v, v), half ? W.y : W.x, acc);
            }
        }
    }
    float lo, hi;
    upk2(acc, lo, hi);
    Y[img * 16384 + (2 * pair) * 1024 + px]     = lo;
    Y[img * 16384 + (2 * pair + 1) * 1024 + px] = hi;
}

// ---------------------------------------------------------------------------
// Quantum: 4 threads per batch element; each owns 4 of 16 output rows.
// ---------------------------------------------------------------------------
__global__ __launch_bounds__(128) void quantum_kernel(
    const float* __restrict__ part, const float* __restrict__ fcb,
    const float2* __restrict__ V, float* __restrict__ qout)
{
    __shared__ float2 sV[256];
    for (int i = threadIdx.x; i < 256; i += 128) sV[i] = V[i];
    __syncthreads();

    const int t = blockIdx.x * 128 + threadIdx.x;
    const int b = t >> 2, sub = t & 3;
    const int i0 = sub * 4;

    float c[4], s[4];
#pragma unroll
    for (int w = 0; w < 4; w++) {
        float ang = part[b * 8 + w] + part[b * 8 + 4 + w] + fcb[w];
        float half = ang * 0.5f;
        c[w] = cosf(half);
        s[w] = sinf(half);
    }

    float2 amp[16];
#pragma unroll
    for (int i = 0; i < 16; i++) {
        float m = ((i >> 3) & 1 ? s[0] : c[0]) * ((i >> 2) & 1 ? s[1] : c[1])
                * ((i >> 1) & 1 ? s[2] : c[2]) * ((i) & 1 ? s[3] : c[3]);
        int pc = __popc(i) & 3;
        amp[i] = (pc == 0) ? make_float2(m, 0.f)
               : (pc == 1) ? make_float2(0.f, -m)
               : (pc == 2) ? make_float2(-m, 0.f)
                           : make_float2(0.f, m);
    }

    float2 tr[4];
#pragma unroll
    for (int r = 0; r < 4; r++) tr[r] = make_float2(0.f, 0.f);
#pragma unroll
    for (int k = 0; k < 16; k++) {
        float2 a = amp[k];
#pragma unroll
        for (int r = 0; r < 4; r++) {
            float2 v = sV[(i0 + r) * 16 + k];
            tr[r].x = fmaf(v.x, a.x, fmaf(-v.y, a.y, tr[r].x));
            tr[r].y = fmaf(v.x, a.y, fmaf(v.y, a.x, tr[r].y));
        }
    }

    float ev[4] = {0.f, 0.f, 0.f, 0.f};
#pragma unroll
    for (int r = 0; r < 4; r++) {
        const int i = i0 + r;
        float p = tr[r].x * tr[r].x + tr[r].y * tr[r].y;
#pragma unroll
        for (int w = 0; w < 4; w++)
            ev[w] += (i & (1 << (3 - w))) ? -p : p;
    }
#pragma unroll
    for (int w = 0; w < 4; w++) {
        ev[w] += __shfl_xor_sync(0xffffffffu, ev[w], 1);
        ev[w] += __shfl_xor_sync(0xffffffffu, ev[w], 2);
    }
    if (sub == 0)
#pragma unroll
        for (int w = 0; w < 4; w++) qout[b * 4 + w] = ev[w];
}

// ---------------------------------------------------------------------------
// Fused output: sY and sH in channel-pair-plane float2 layout; K-packed
// dconv2 (216 fma2/px, pure LDS.64 taps). 8 passes x 2 batches x 256 thr.
// ---------------------------------------------------------------------------
#define FP 340    // per (img,cp) plane in ull (10 rows x 34 cols)
__global__ __launch_bounds__(512) void fused_out_kernel(
    const float* __restrict__ q, const float* __restrict__ Y,
    const float* __restrict__ bias, float* __restrict__ out)
{
    extern __shared__ ull usm[];
    ull* sY = usm;                 // [img<5][cp<8][px<340]
    ull* sH = usm + 5 * 8 * FP;    // [half<2][cp<8][px<340]

    __shared__ float s_b[3];

    const int ck = blockIdx.x;
    const int y0 = ck * 8;
    const int b0 = blockIdx.y * 16;
    const int tid  = threadIdx.x;
    const int half = tid >> 8;
    const int htid = tid & 255;

    if (tid < 3) s_b[tid] = bias[tid];

    if (tid < 340) {
        const int r = tid / 34, xc = tid - 34 * r;
        const int gy = y0 + r - 1, gx = xc - 1;
        const bool ok = ((unsigned)gy < 32u) && ((unsigned)gx < 32u);
        const int goff = gy * 32 + gx;
#pragma unroll
        for (int img = 0; img < 5; img++)
#pragma unroll
            for (int cp = 0; cp < 8; cp++) {
                float a = 0.f, bb = 0.f;
                if (ok) {
                    a  = __ldg(Y + img * 16384 + (2 * cp) * 1024 + goff);
                    bb = __ldg(Y + img * 16384 + (2 * cp + 1) * 1024 + goff);
                }
                sY[(img * 8 + cp) * FP + tid] = pk2(a, bb);
            }
    }
    __syncthreads();

    const int tx = htid & 31, ty = htid >> 5;
    ull* sHh = sH + half * 8 * FP;

    for (int g = 0; g < 8; g++) {
        const int b = b0 + 2 * g + half;
        const float q0 = __ldg(q + b * 4 + 0), q1 = __ldg(q + b * 4 + 1);
        const float q2 = __ldg(q + b * 4 + 2), q3 = __ldg(q + b * 4 + 3);
        const ull Q0 = pk2(q0, q0), Q1 = pk2(q1, q1);
        const ull Q2 = pk2(q2, q2), Q3 = pk2(q3, q3);

        // combine + relu over pair planes (i = cp*FP + px)
        for (int i = htid; i < 8 * FP; i += 256) {
            ull v = fma2(Q0, sY[i],
                    fma2(Q1, sY[8 * FP + i],
                    fma2(Q2, sY[16 * FP + i],
                    fma2(Q3, sY[24 * FP + i], sY[32 * FP + i]))));
            float lo, hi;
            upk2(v, lo, hi);
            sHh[i] = pk2(fmaxf(lo, 0.f), fmaxf(hi, 0.f));
        }
        __syncthreads();

        // dconv2 K-packed (16->3) + sigmoid
        ull acc[3];
#pragma unroll
        for (int co = 0; co < 3; co++) acc[co] = pk2(s_b[co], 0.f);
#pragma unroll
        for (int cp = 0; cp < 8; cp++) {
            ull v[9];
#pragma unroll
            for (int dy = 0; dy < 3; dy++)
#pragma unroll
                for (int dx = 0; dx < 3; dx++)
                    v[dy * 3 + dx] = sHh[cp * FP + (ty + dy) * 34 + tx + dx];
#pragma unroll
            for (int k = 0; k < 9; k++) {
#pragma unroll
                for (int co = 0; co < 3; co++)
                    acc[co] = fma2(v[k], c_w.wdp2[(cp * 9 + k) * 3 + co], acc[co]);
            }
        }
        float* outp = out + (size_t)b * 3 * 1024 + (y0 + ty) * 32 + tx;
#pragma unroll
        for (int co = 0; co < 3; co++) {
            float lo, hi;
            upk2(acc[co], lo, hi);
            outp[co * 1024] = __fdividef(1.f, 1.f + __expf(-(lo + hi)));
        }
        __syncthreads();
    }
}

// ---------------------------------------------------------------------------

extern "C" void kernel_launch(void* const* d_in, const int* in_sizes, int n_in,
                              void* d_out, int out_size)
{
    const float* x   = (const float*)d_in[0];
    const float* c1w = (const float*)d_in[1];
    const float* c1b = (const float*)d_in[2];
    const float* c2w = (const float*)d_in[3];
    const float* c2b = (const float*)d_in[4];
    const float* fcw = (const float*)d_in[5];
    const float* fcb = (const float*)d_in[6];
    const float* qw  = (const float*)d_in[7];
    const float* f2w = (const float*)d_in[8];
    const float* f2b = (const float*)d_in[9];
    const float* d1w = (const float*)d_in[10];
    const float* d1b = (const float*)d_in[11];
    const float* d2w = (const float*)d_in[12];
    const float* d2b = (const float*)d_in[13];
    float* out = (float*)d_out;

    float *part, *qv, *Y, *pk;
    float2* V;
    cudaGetSymbolAddress((void**)&part, g_part);
    cudaGetSymbolAddress((void**)&qv,   g_q);
    cudaGetSymbolAddress((void**)&Y,    g_Y);
    cudaGetSymbolAddress((void**)&V,    g_V);
    cudaGetSymbolAddress((void**)&pk,   g_pk);

    const int conv12_smem = XSZ2 * 4 + 8 * H1P * 8;       // 47328 B
    const int fo_smem     = (5 + 2) * 8 * FP * 8;         // 152320 B

    cudaFuncSetAttribute(conv12_kernel,
                         cudaFuncAttributeMaxDynamicSharedMemorySize, conv12_smem);
    cudaFuncSetAttribute(fused_out_kernel,
                         cudaFuncAttributeMaxDynamicSharedMemorySize, fo_smem);

    setup_kernel<<<8, 256>>>(c1w, c2w, d1w, d2w, qw, V);
    cudaMemcpyToSymbolAsync(c_w, pk, sizeof(CW), 0, cudaMemcpyDeviceToDevice, 0);

    ybuild_kernel<<<160, 256>>>(f2w, f2b, d1b, Y);
    probe_kernel<<<1, 32>>>();
    conv12_kernel<<<dim3(2, BATCH), 576, conv12_smem>>>(x, c1b, c2b, fcw, part);
    quantum_kernel<<<BATCH / 32, 128>>>(part, fcb, V, qv);
    fused_out_kernel<<<dim3(4, BATCH / 16), 512, fo_smem>>>(qv, Y, d2b, out);
}